// round 9
// baseline (speedup 1.0000x reference)
#include <cuda_runtime.h>
#include <cuda_bf16.h>
#include <cstdint>

#define K1REAL  100
#define HDIM    256
#define TILE_M  128
#define THREADS 512            // 16 warps: m-warp (wid&3)*32, n-warp (wid>>2)*64
#define NCHUNK  40             // k16 chunks: L1 8 (k pad 128), L2 16, L3 16

#define WIMG_B   8192          // 256 n x 32B (k16), packed 4n/128B line
#define WCHUNK_B 16384         // hi + lo
#define SM_ACT_HI 0            // 128 x 512B, XOR-swizzled
#define SM_ACT_LO 65536
#define SM_WBUF   131072       // 4 x 16384
#define SMEM_TOTAL 196608

// pre-split, pre-packed weights: [chunk][hi|lo][packed img]
__device__ __nv_bfloat16 WCH[(size_t)NCHUNK * 8192];

__device__ __forceinline__ uint32_t smem_u32(const void* p) {
    uint32_t a;
    asm("{ .reg .u64 t; cvta.to.shared.u64 t, %1; cvt.u32.u64 %0, t; }" : "=r"(a) : "l"(p));
    return a;
}
__device__ __forceinline__ void ldsm_x4(uint32_t r[4], uint32_t addr) {
    asm volatile("ldmatrix.sync.aligned.m8n8.x4.shared.b16 {%0,%1,%2,%3}, [%4];"
                 : "=r"(r[0]), "=r"(r[1]), "=r"(r[2]), "=r"(r[3]) : "r"(addr));
}
__device__ __forceinline__ void mma_bf16(float d[4], const uint32_t a[4],
                                         uint32_t b0, uint32_t b1) {
    asm volatile(
        "mma.sync.aligned.m16n8k16.row.col.f32.bf16.bf16.f32 "
        "{%0,%1,%2,%3}, {%4,%5,%6,%7}, {%8,%9}, {%0,%1,%2,%3};"
        : "+f"(d[0]), "+f"(d[1]), "+f"(d[2]), "+f"(d[3])
        : "r"(a[0]), "r"(a[1]), "r"(a[2]), "r"(a[3]), "r"(b0), "r"(b1));
}
__device__ __forceinline__ float tanh_fast(float x) {
    float y; asm("tanh.approx.f32 %0, %1;" : "=f"(y) : "f"(x)); return y;
}
__device__ __forceinline__ uint32_t pack_bf2(float a, float b) {
    __nv_bfloat162 t;
    t.x = __float2bfloat16(a); t.y = __float2bfloat16(b);
    return *reinterpret_cast<uint32_t*>(&t);
}
// act element (m, k): byte offset m*512 + ((k*2) ^ ((m&7)<<4))
__device__ __forceinline__ uint32_t act_off(int m, int k) {
    return (uint32_t)m * 512u + (((uint32_t)k * 2u) ^ (((uint32_t)m & 7u) << 4));
}

// ---- weight pre-split/pack: W[k][n] -> WCH[g][hi|lo] packed ----
__global__ void wsplit_kernel(const float* __restrict__ W1,
                              const float* __restrict__ W2,
                              const float* __restrict__ W3) {
    int n = threadIdx.x;
    int kidx = blockIdx.x;                  // 0..639 padded k
    const float* W; int kk, Kreal, g;
    if (kidx < 128)      { kk = kidx;       W = W1; Kreal = K1REAL; g = kk >> 4; }
    else if (kidx < 384) { kk = kidx - 128; W = W2; Kreal = HDIM;   g = 8  + (kk >> 4); }
    else                 { kk = kidx - 384; W = W3; Kreal = HDIM;   g = 24 + (kk >> 4); }
    float w = (kk < Kreal) ? W[kk * HDIM + n] : 0.0f;
    __nv_bfloat16 hi = __float2bfloat16(w);
    __nv_bfloat16 lo = __float2bfloat16(w - __bfloat162float(hi));
    uint32_t pos = (uint32_t)(n >> 2) * 128u
                 + ((((uint32_t)(n & 3) * 32u) + (uint32_t)((kk >> 3) & 1) * 16u)
                    ^ (((uint32_t)(n >> 2) & 1u) << 4))
                 + (uint32_t)(kk & 7) * 2u;
    WCH[(size_t)g * 8192 + (pos >> 1)]        = hi;
    WCH[(size_t)g * 8192 + 4096 + (pos >> 1)] = lo;
}

// ---- main kernel ----
__global__ void __launch_bounds__(THREADS, 1)
gnn_mma_kernel(const float* __restrict__ ea,
               const float* __restrict__ b1, const float* __restrict__ b2,
               const float* __restrict__ b3,
               const float* __restrict__ W4, const float* __restrict__ b4,
               float* __restrict__ out, int ntot)
{
    extern __shared__ char smem[];
    const uint32_t sbase = smem_u32(smem);
    const int tid = threadIdx.x, lane = tid & 31, wid = tid >> 5;
    const int m0 = (wid & 3) * 32, n0 = (wid >> 2) * 64;
    const int row0 = blockIdx.x * TILE_M;

    // prefetch chunks 0..2 (one commit-group each)
#pragma unroll
    for (int p = 0; p < 3; p++) {
        const char* src = (const char*)WCH + (size_t)p * WCHUNK_B;
        uint32_t dst = sbase + SM_WBUF + p * WCHUNK_B;
#pragma unroll
        for (int i = 0; i < 2; i++) {
            int off = (tid + i * THREADS) * 16;
            asm volatile("cp.async.cg.shared.global [%0], [%1], 16;"
                         :: "r"(dst + off), "l"(src + off));
        }
        asm volatile("cp.async.commit_group;");
    }

    // e-tile: [m][k0..127] bf16 hi/lo, swizzled (k>=100 zero)
#pragma unroll
    for (int i = 0; i < 32; i++) {
        int idx = tid + i * THREADS;        // 128*128
        int m = idx >> 7, k = idx & 127;
        int row = row0 + m;
        float v = (k < K1REAL && row < ntot) ? ea[(size_t)row * K1REAL + k] : 0.0f;
        __nv_bfloat16 hi = __float2bfloat16(v);
        __nv_bfloat16 lo = __float2bfloat16(v - __bfloat162float(hi));
        uint32_t off = act_off(m, k);
        *(__nv_bfloat16*)(smem + SM_ACT_HI + off) = hi;
        *(__nv_bfloat16*)(smem + SM_ACT_LO + off) = lo;
    }

    // per-lane ldmatrix addressing (loop-invariant parts)
    const int midx = lane >> 3, l7 = lane & 7;
    const int a_row  = m0 + (midx & 1) * 8 + l7;
    const uint32_t a_base = (uint32_t)a_row * 512u;
    const uint32_t a_sw   = ((uint32_t)a_row & 7u) << 4;
    const uint32_t a_k2   = (uint32_t)(midx >> 1) * 16u;   // k-offset bytes
    uint32_t boff[4];
#pragma unroll
    for (int ng = 0; ng < 4; ng++) {
        int nn = n0 + ng * 16 + (midx >> 1) * 8 + l7;
        boff[ng] = (uint32_t)(nn >> 2) * 128u
                 + ((((uint32_t)(nn & 3) * 32u) + (uint32_t)(midx & 1) * 16u)
                    ^ (((uint32_t)(nn >> 2) & 1u) << 4));
    }

    float acc[2][8][4];
#pragma unroll
    for (int mt = 0; mt < 2; mt++)
#pragma unroll
        for (int nt = 0; nt < 8; nt++)
#pragma unroll
            for (int q = 0; q < 4; q++) acc[mt][nt][q] = 0.0f;

    int l = 0, lend = 7, lstart = 0;
    const int r = lane >> 2, cp2 = (lane & 3) * 2;

    for (int g = 0; g < NCHUNK; g++) {
        asm volatile("cp.async.wait_group 2;" ::: "memory");   // chunk g landed
        __syncthreads();   // chunk g visible block-wide; buf[(g+3)&3] readers done
        {   // prefetch g+3 (empty commit keeps group accounting exact)
            if (g + 3 < NCHUNK) {
                const char* src = (const char*)WCH + (size_t)(g + 3) * WCHUNK_B;
                uint32_t dst = sbase + SM_WBUF + ((g + 3) & 3) * WCHUNK_B;
#pragma unroll
                for (int i = 0; i < 2; i++) {
                    int off = (tid + i * THREADS) * 16;
                    asm volatile("cp.async.cg.shared.global [%0], [%1], 16;"
                                 :: "r"(dst + off), "l"(src + off));
                }
            }
            asm volatile("cp.async.commit_group;");
        }

        const uint32_t whi = sbase + SM_WBUF + (g & 3) * WCHUNK_B;
        const uint32_t wlo = whi + WIMG_B;
        const uint32_t axk = (((uint32_t)(g - lstart) * 32u) + a_k2) ^ a_sw;
        const uint32_t aoff = sbase + SM_ACT_HI + a_base + axk;

        uint32_t ah[2][4], al[2][4], bh[16], bl_[16];
        ldsm_x4(ah[0], aoff);
        ldsm_x4(ah[1], aoff + 8192);
        ldsm_x4(al[0], aoff + 65536);
        ldsm_x4(al[1], aoff + 65536 + 8192);
#pragma unroll
        for (int ng = 0; ng < 4; ng++) ldsm_x4(bh + ng * 4, whi + boff[ng]);
#pragma unroll
        for (int ng = 0; ng < 4; ng++) ldsm_x4(bl_ + ng * 4, wlo + boff[ng]);

#pragma unroll
        for (int nt = 0; nt < 8; nt++) {
            uint32_t bx = bh[(nt >> 1) * 4 + (nt & 1) * 2];
            uint32_t by = bh[(nt >> 1) * 4 + (nt & 1) * 2 + 1];
            mma_bf16(acc[0][nt], ah[0], bx, by);
            mma_bf16(acc[1][nt], ah[1], bx, by);
        }
#pragma unroll
        for (int nt = 0; nt < 8; nt++) {
            uint32_t bx = bh[(nt >> 1) * 4 + (nt & 1) * 2];
            uint32_t by = bh[(nt >> 1) * 4 + (nt & 1) * 2 + 1];
            mma_bf16(acc[0][nt], al[0], bx, by);
            mma_bf16(acc[1][nt], al[1], bx, by);
        }
#pragma unroll
        for (int nt = 0; nt < 8; nt++) {
            uint32_t bx = bl_[(nt >> 1) * 4 + (nt & 1) * 2];
            uint32_t by = bl_[(nt >> 1) * 4 + (nt & 1) * 2 + 1];
            mma_bf16(acc[0][nt], ah[0], bx, by);
            mma_bf16(acc[1][nt], ah[1], bx, by);
        }

        if (g == lend) {
            __syncthreads();   // all act reads of this layer done
            const float* bl = (l == 0) ? b1 : (l == 1) ? b2 : b3;
#pragma unroll
            for (int nt = 0; nt < 8; nt++) {
                int n = n0 + nt * 8 + cp2;
                float bn0 = __ldg(bl + n), bn1 = __ldg(bl + n + 1);
#pragma unroll
                for (int mt = 0; mt < 2; mt++)
#pragma unroll
                    for (int dp = 0; dp < 2; dp++) {
                        int m = m0 + mt * 16 + r + dp * 8;
                        float t0 = tanh_fast(acc[mt][nt][dp * 2]     + bn0);
                        float t1 = tanh_fast(acc[mt][nt][dp * 2 + 1] + bn1);
                        float h0 = __bfloat162float(__float2bfloat16(t0));
                        float h1 = __bfloat162float(__float2bfloat16(t1));
                        uint32_t off = act_off(m, n);
                        *(uint32_t*)(smem + SM_ACT_HI + off) = pack_bf2(t0, t1);
                        *(uint32_t*)(smem + SM_ACT_LO + off) = pack_bf2(t0 - h0, t1 - h1);
                        acc[mt][nt][dp * 2] = 0.0f; acc[mt][nt][dp * 2 + 1] = 0.0f;
                    }
            }
            l++; lstart = g + 1; lend += 16;
            // next iteration's __syncthreads orders act writes before ldsm reads
        }
    }
    __syncthreads();

    // layer 4: out[m] = sigmoid( sum_k act[m][k]*W4[k] + b4 ), 4 thr/row
    {
        int m = tid >> 2, seg = tid & 3;
        uint32_t base = (uint32_t)m * 512u, sw = ((uint32_t)m & 7u) << 4;
        float s = 0.f;
#pragma unroll
        for (int q = 0; q < 32; q++) {
            uint32_t off = base + (((uint32_t)(seg * 128 + q * 4)) ^ sw);
            __nv_bfloat162 h2 = *(const __nv_bfloat162*)(smem + SM_ACT_HI + off);
            __nv_bfloat162 l2 = *(const __nv_bfloat162*)(smem + SM_ACT_LO + off);
            float2 w2 = __ldg((const float2*)(W4 + seg * 64 + q * 2));
            s += (__bfloat162float(h2.x) + __bfloat162float(l2.x)) * w2.x
               + (__bfloat162float(h2.y) + __bfloat162float(l2.y)) * w2.y;
        }
        s += __shfl_down_sync(0xffffffff, s, 2);
        s += __shfl_down_sync(0xffffffff, s, 1);
        if (seg == 0) {
            float z = s + __ldg(b4);
            int row = row0 + m;
            if (row < ntot) out[row] = 1.0f / (1.0f + expf(-z));
        }
    }
}

extern "C" void kernel_launch(void* const* d_in, const int* in_sizes, int n_in,
                              void* d_out, int out_size)
{
    // Inputs: x, edge_index, edge_attr, W1, b1, W2, b2, W3, b3, W4, b4
    const float* ea = (const float*)d_in[2];
    const float* W1 = (const float*)d_in[3];
    const float* b1 = (const float*)d_in[4];
    const float* W2 = (const float*)d_in[5];
    const float* b2 = (const float*)d_in[6];
    const float* W3 = (const float*)d_in[7];
    const float* b3 = (const float*)d_in[8];
    const float* W4 = (const float*)d_in[9];
    const float* b4 = (const float*)d_in[10];
    float* out = (float*)d_out;

    int ntot = out_size;                              // 500000
    int grid = (ntot + TILE_M - 1) / TILE_M;          // 3907

    wsplit_kernel<<<640, 256>>>(W1, W2, W3);

    cudaFuncSetAttribute(gnn_mma_kernel,
                         cudaFuncAttributeMaxDynamicSharedMemorySize, SMEM_TOTAL);
    gnn_mma_kernel<<<grid, THREADS, SMEM_TOTAL>>>(ea, b1, b2, b3, W4, b4, out, ntot);
}

// round 10
// speedup vs baseline: 1.2020x; 1.2020x over previous
#include <cuda_runtime.h>
#include <cuda_bf16.h>
#include <cstdint>

#define K1REAL  100
#define HDIM    256
#define TILE_M  64
#define THREADS 256            // 8 warps: m-warp (wid&1)*32, n-warp (wid>>1)*64
#define NCHUNK  40             // k16 chunks: L1 8 (k pad 128), L2 16, L3 16

#define WIMG_B   8192          // 256 n x 32B (k16), packed 4n/128B line
#define WCHUNK_B 16384         // hi + lo
#define SM_ACT_HI 0            // 64 x 512B, XOR-swizzled
#define SM_ACT_LO 32768
#define SM_WBUF   65536        // 3 x 16384
#define SMEM_TOTAL 114688      // 112 KB -> 2 CTAs/SM

// pre-split, pre-packed weights: [chunk][hi|lo][packed img]
__device__ __nv_bfloat16 WCH[(size_t)NCHUNK * 8192];

__device__ __forceinline__ uint32_t smem_u32(const void* p) {
    uint32_t a;
    asm("{ .reg .u64 t; cvta.to.shared.u64 t, %1; cvt.u32.u64 %0, t; }" : "=r"(a) : "l"(p));
    return a;
}
__device__ __forceinline__ void ldsm_x4(uint32_t r[4], uint32_t addr) {
    asm volatile("ldmatrix.sync.aligned.m8n8.x4.shared.b16 {%0,%1,%2,%3}, [%4];"
                 : "=r"(r[0]), "=r"(r[1]), "=r"(r[2]), "=r"(r[3]) : "r"(addr));
}
__device__ __forceinline__ void mma_bf16(float d[4], const uint32_t a[4],
                                         uint32_t b0, uint32_t b1) {
    asm volatile(
        "mma.sync.aligned.m16n8k16.row.col.f32.bf16.bf16.f32 "
        "{%0,%1,%2,%3}, {%4,%5,%6,%7}, {%8,%9}, {%0,%1,%2,%3};"
        : "+f"(d[0]), "+f"(d[1]), "+f"(d[2]), "+f"(d[3])
        : "r"(a[0]), "r"(a[1]), "r"(a[2]), "r"(a[3]), "r"(b0), "r"(b1));
}
__device__ __forceinline__ float tanh_fast(float x) {
    float y; asm("tanh.approx.f32 %0, %1;" : "=f"(y) : "f"(x)); return y;
}
__device__ __forceinline__ uint32_t pack_bf2(float a, float b) {
    __nv_bfloat162 t;
    t.x = __float2bfloat16(a); t.y = __float2bfloat16(b);
    return *reinterpret_cast<uint32_t*>(&t);
}
// act element (m, k): byte offset m*512 + ((k*2) ^ ((m&7)<<4))
__device__ __forceinline__ uint32_t act_off(int m, int k) {
    return (uint32_t)m * 512u + (((uint32_t)k * 2u) ^ (((uint32_t)m & 7u) << 4));
}

// ---- weight pre-split/pack: W[k][n] -> WCH[g][hi|lo] packed (verified R8/R9) ----
__global__ void wsplit_kernel(const float* __restrict__ W1,
                              const float* __restrict__ W2,
                              const float* __restrict__ W3) {
    int n = threadIdx.x;
    int kidx = blockIdx.x;                  // 0..639 padded k
    const float* W; int kk, Kreal, g;
    if (kidx < 128)      { kk = kidx;       W = W1; Kreal = K1REAL; g = kk >> 4; }
    else if (kidx < 384) { kk = kidx - 128; W = W2; Kreal = HDIM;   g = 8  + (kk >> 4); }
    else                 { kk = kidx - 384; W = W3; Kreal = HDIM;   g = 24 + (kk >> 4); }
    float w = (kk < Kreal) ? W[kk * HDIM + n] : 0.0f;
    __nv_bfloat16 hi = __float2bfloat16(w);
    __nv_bfloat16 lo = __float2bfloat16(w - __bfloat162float(hi));
    uint32_t pos = (uint32_t)(n >> 2) * 128u
                 + ((((uint32_t)(n & 3) * 32u) + (uint32_t)((kk >> 3) & 1) * 16u)
                    ^ (((uint32_t)(n >> 2) & 1u) << 4))
                 + (uint32_t)(kk & 7) * 2u;
    WCH[(size_t)g * 8192 + (pos >> 1)]        = hi;
    WCH[(size_t)g * 8192 + 4096 + (pos >> 1)] = lo;
}

// ---- main kernel ----
__global__ void __launch_bounds__(THREADS, 2)
gnn_mma_kernel(const float* __restrict__ ea,
               const float* __restrict__ b1, const float* __restrict__ b2,
               const float* __restrict__ b3,
               const float* __restrict__ W4, const float* __restrict__ b4,
               float* __restrict__ out, int ntot)
{
    extern __shared__ char smem[];
    const uint32_t sbase = smem_u32(smem);
    const int tid = threadIdx.x, lane = tid & 31, wid = tid >> 5;
    const int m0 = (wid & 1) * 32, n0 = (wid >> 1) * 64;
    const int row0 = blockIdx.x * TILE_M;

    // prefetch chunks 0,1 (one commit-group each)
#pragma unroll
    for (int p = 0; p < 2; p++) {
        const char* src = (const char*)WCH + (size_t)p * WCHUNK_B;
        uint32_t dst = sbase + SM_WBUF + p * WCHUNK_B;
#pragma unroll
        for (int i = 0; i < 4; i++) {
            int off = (tid + i * THREADS) * 16;
            asm volatile("cp.async.cg.shared.global [%0], [%1], 16;"
                         :: "r"(dst + off), "l"(src + off));
        }
        asm volatile("cp.async.commit_group;");
    }

    // e-tile: [m][k0..127] bf16 hi/lo, swizzled (k>=100 zero)
#pragma unroll
    for (int i = 0; i < 32; i++) {
        int idx = tid + i * THREADS;        // 64*128
        int m = idx >> 7, k = idx & 127;
        int row = row0 + m;
        float v = (k < K1REAL && row < ntot) ? ea[(size_t)row * K1REAL + k] : 0.0f;
        __nv_bfloat16 hi = __float2bfloat16(v);
        __nv_bfloat16 lo = __float2bfloat16(v - __bfloat162float(hi));
        uint32_t off = act_off(m, k);
        *(__nv_bfloat16*)(smem + SM_ACT_HI + off) = hi;
        *(__nv_bfloat16*)(smem + SM_ACT_LO + off) = lo;
    }

    // per-lane ldmatrix addressing (loop-invariant parts)
    const int midx = lane >> 3, l7 = lane & 7;
    const int a_row  = m0 + (midx & 1) * 8 + l7;
    const uint32_t a_base = (uint32_t)a_row * 512u;
    const uint32_t a_sw   = ((uint32_t)a_row & 7u) << 4;
    const uint32_t a_k2   = (uint32_t)(midx >> 1) * 16u;
    uint32_t boff[4];
#pragma unroll
    for (int ng = 0; ng < 4; ng++) {
        int nn = n0 + ng * 16 + (midx >> 1) * 8 + l7;
        boff[ng] = (uint32_t)(nn >> 2) * 128u
                 + ((((uint32_t)(nn & 3) * 32u) + (uint32_t)(midx & 1) * 16u)
                    ^ (((uint32_t)(nn >> 2) & 1u) << 4));
    }

    float acc[2][8][4];
#pragma unroll
    for (int mt = 0; mt < 2; mt++)
#pragma unroll
        for (int nt = 0; nt < 8; nt++)
#pragma unroll
            for (int q = 0; q < 4; q++) acc[mt][nt][q] = 0.0f;

    int l = 0, lend = 7, lstart = 0;
    const int r = lane >> 2, cp2 = (lane & 3) * 2;

    for (int g = 0; g < NCHUNK; g++) {
        asm volatile("cp.async.wait_group 1;" ::: "memory");   // chunk g landed
        __syncthreads();   // chunk g visible; buf[(g+2)%3] readers (chunk g-1) done
        {   // prefetch g+2 (empty commit keeps group accounting exact)
            if (g + 2 < NCHUNK) {
                const char* src = (const char*)WCH + (size_t)(g + 2) * WCHUNK_B;
                uint32_t dst = sbase + SM_WBUF + ((g + 2) % 3) * WCHUNK_B;
#pragma unroll
                for (int i = 0; i < 4; i++) {
                    int off = (tid + i * THREADS) * 16;
                    asm volatile("cp.async.cg.shared.global [%0], [%1], 16;"
                                 :: "r"(dst + off), "l"(src + off));
                }
            }
            asm volatile("cp.async.commit_group;");
        }

        const uint32_t whi = sbase + SM_WBUF + (g % 3) * WCHUNK_B;
        const uint32_t wlo = whi + WIMG_B;
        const uint32_t axk = (((uint32_t)(g - lstart) * 32u) + a_k2) ^ a_sw;
        const uint32_t aoff = sbase + SM_ACT_HI + a_base + axk;

        uint32_t ah[2][4], al[2][4], bh[16], bl_[16];
        ldsm_x4(ah[0], aoff);
        ldsm_x4(ah[1], aoff + 8192);
        ldsm_x4(al[0], aoff + 32768);
        ldsm_x4(al[1], aoff + 32768 + 8192);
#pragma unroll
        for (int ng = 0; ng < 4; ng++) ldsm_x4(bh + ng * 4, whi + boff[ng]);
#pragma unroll
        for (int ng = 0; ng < 4; ng++) ldsm_x4(bl_ + ng * 4, wlo + boff[ng]);

#pragma unroll
        for (int nt = 0; nt < 8; nt++) {
            uint32_t bx = bh[(nt >> 1) * 4 + (nt & 1) * 2];
            uint32_t by = bh[(nt >> 1) * 4 + (nt & 1) * 2 + 1];
            mma_bf16(acc[0][nt], ah[0], bx, by);
            mma_bf16(acc[1][nt], ah[1], bx, by);
        }
#pragma unroll
        for (int nt = 0; nt < 8; nt++) {
            uint32_t bx = bh[(nt >> 1) * 4 + (nt & 1) * 2];
            uint32_t by = bh[(nt >> 1) * 4 + (nt & 1) * 2 + 1];
            mma_bf16(acc[0][nt], al[0], bx, by);
            mma_bf16(acc[1][nt], al[1], bx, by);
        }
#pragma unroll
        for (int nt = 0; nt < 8; nt++) {
            uint32_t bx = bl_[(nt >> 1) * 4 + (nt & 1) * 2];
            uint32_t by = bl_[(nt >> 1) * 4 + (nt & 1) * 2 + 1];
            mma_bf16(acc[0][nt], ah[0], bx, by);
            mma_bf16(acc[1][nt], ah[1], bx, by);
        }

        if (g == lend) {
            __syncthreads();   // all act reads of this layer done
            const float* bl = (l == 0) ? b1 : (l == 1) ? b2 : b3;
#pragma unroll
            for (int nt = 0; nt < 8; nt++) {
                int n = n0 + nt * 8 + cp2;
                float bn0 = __ldg(bl + n), bn1 = __ldg(bl + n + 1);
#pragma unroll
                for (int mt = 0; mt < 2; mt++)
#pragma unroll
                    for (int dp = 0; dp < 2; dp++) {
                        int m = m0 + mt * 16 + r + dp * 8;
                        float t0 = tanh_fast(acc[mt][nt][dp * 2]     + bn0);
                        float t1 = tanh_fast(acc[mt][nt][dp * 2 + 1] + bn1);
                        float h0 = __bfloat162float(__float2bfloat16(t0));
                        float h1 = __bfloat162float(__float2bfloat16(t1));
                        uint32_t off = act_off(m, n);
                        *(uint32_t*)(smem + SM_ACT_HI + off) = pack_bf2(t0, t1);
                        *(uint32_t*)(smem + SM_ACT_LO + off) = pack_bf2(t0 - h0, t1 - h1);
                        acc[mt][nt][dp * 2] = 0.0f; acc[mt][nt][dp * 2 + 1] = 0.0f;
                    }
            }
            l++; lstart = g + 1; lend += 16;
            // next iteration's __syncthreads orders act writes before ldsm reads
        }
    }
    __syncthreads();

    // layer 4: out[m] = sigmoid( sum_k act[m][k]*W4[k] + b4 ), 4 thr/row
    {
        int m = tid >> 2, seg = tid & 3;
        uint32_t base = (uint32_t)m * 512u, sw = ((uint32_t)m & 7u) << 4;
        float s = 0.f;
#pragma unroll
        for (int q = 0; q < 32; q++) {
            uint32_t off = base + (((uint32_t)(seg * 128 + q * 4)) ^ sw);
            __nv_bfloat162 h2 = *(const __nv_bfloat162*)(smem + SM_ACT_HI + off);
            __nv_bfloat162 l2 = *(const __nv_bfloat162*)(smem + SM_ACT_LO + off);
            float2 w2 = __ldg((const float2*)(W4 + seg * 64 + q * 2));
            s += (__bfloat162float(h2.x) + __bfloat162float(l2.x)) * w2.x
               + (__bfloat162float(h2.y) + __bfloat162float(l2.y)) * w2.y;
        }
        s += __shfl_down_sync(0xffffffff, s, 2);
        s += __shfl_down_sync(0xffffffff, s, 1);
        if (seg == 0) {
            float z = s + __ldg(b4);
            int row = row0 + m;
            if (row < ntot) out[row] = 1.0f / (1.0f + expf(-z));
        }
    }
}

extern "C" void kernel_launch(void* const* d_in, const int* in_sizes, int n_in,
                              void* d_out, int out_size)
{
    // Inputs: x, edge_index, edge_attr, W1, b1, W2, b2, W3, b3, W4, b4
    const float* ea = (const float*)d_in[2];
    const float* W1 = (const float*)d_in[3];
    const float* b1 = (const float*)d_in[4];
    const float* W2 = (const float*)d_in[5];
    const float* b2 = (const float*)d_in[6];
    const float* W3 = (const float*)d_in[7];
    const float* b3 = (const float*)d_in[8];
    const float* W4 = (const float*)d_in[9];
    const float* b4 = (const float*)d_in[10];
    float* out = (float*)d_out;

    int ntot = out_size;                              // 500000
    int grid = (ntot + TILE_M - 1) / TILE_M;          // 7813

    wsplit_kernel<<<640, 256>>>(W1, W2, W3);

    cudaFuncSetAttribute(gnn_mma_kernel,
                         cudaFuncAttributeMaxDynamicSharedMemorySize, SMEM_TOTAL);
    gnn_mma_kernel<<<grid, THREADS, SMEM_TOTAL>>>(ea, b1, b2, b3, W4, b4, out, ntot);
}

// round 11
// speedup vs baseline: 1.3833x; 1.1508x over previous
#include <cuda_runtime.h>
#include <cuda_bf16.h>
#include <cstdint>

#define K1REAL  100
#define HDIM    256
#define TILE_M  64
#define THREADS 256            // 8 warps; warp w owns m0..63 x n[w*32, w*32+32)
#define NCHUNK  40             // k16 chunks: L1 8 (k pad 128), L2 16, L3 16

#define SM_ACT_HI 0            // 64 x 512B, XOR-swizzled
#define SM_ACT_LO 32768
#define SMEM_TOTAL 65536       // act only -> no weight smem at all

// fragment-linear weights: per (chunk, img) 8192B; per warp-slice 1024B;
// lane L's ldsm-equivalent quads at L*16 (q0) and 512+L*16 (q1)
__device__ __nv_bfloat16 WCH[(size_t)NCHUNK * 2 * 4096];

__device__ __forceinline__ uint32_t smem_u32(const void* p) {
    uint32_t a;
    asm("{ .reg .u64 t; cvta.to.shared.u64 t, %1; cvt.u32.u64 %0, t; }" : "=r"(a) : "l"(p));
    return a;
}
__device__ __forceinline__ void ldsm_x4(uint32_t r[4], uint32_t addr) {
    asm volatile("ldmatrix.sync.aligned.m8n8.x4.shared.b16 {%0,%1,%2,%3}, [%4];"
                 : "=r"(r[0]), "=r"(r[1]), "=r"(r[2]), "=r"(r[3]) : "r"(addr));
}
__device__ __forceinline__ void mma_bf16(float d[4], const uint32_t a[4],
                                         uint32_t b0, uint32_t b1) {
    asm volatile(
        "mma.sync.aligned.m16n8k16.row.col.f32.bf16.bf16.f32 "
        "{%0,%1,%2,%3}, {%4,%5,%6,%7}, {%8,%9}, {%0,%1,%2,%3};"
        : "+f"(d[0]), "+f"(d[1]), "+f"(d[2]), "+f"(d[3])
        : "r"(a[0]), "r"(a[1]), "r"(a[2]), "r"(a[3]), "r"(b0), "r"(b1));
}
__device__ __forceinline__ float tanh_fast(float x) {
    float y; asm("tanh.approx.f32 %0, %1;" : "=f"(y) : "f"(x)); return y;
}
__device__ __forceinline__ uint32_t pack_bf2(float a, float b) {
    __nv_bfloat162 t;
    t.x = __float2bfloat16(a); t.y = __float2bfloat16(b);
    return *reinterpret_cast<uint32_t*>(&t);
}
// act element (m, k): byte offset m*512 + ((k*2) ^ ((m&7)<<4))  (verified R8-R10)
__device__ __forceinline__ uint32_t act_off(int m, int k) {
    return (uint32_t)m * 512u + (((uint32_t)k * 2u) ^ (((uint32_t)m & 7u) << 4));
}

// ---- weight pre-split into fragment-linear layout ----
// reg j of lane L of warp-slice s, quad-group q holds bf16 pair:
//   n = s*32 + q*16 + (j>>1)*8 + L/4,  k = (j&1)*8 + (L%4)*2 (+0,+1)
// (derived from ldmatrix semantics; R10 packing verified bit-identical)
__global__ void wsplit_kernel(const float* __restrict__ W1,
                              const float* __restrict__ W2,
                              const float* __restrict__ W3) {
    int n = threadIdx.x;
    int kidx = blockIdx.x;                  // 0..639 padded k
    const float* W; int kk, Kreal, g;
    if (kidx < 128)      { kk = kidx;       W = W1; Kreal = K1REAL; g = kk >> 4; }
    else if (kidx < 384) { kk = kidx - 128; W = W2; Kreal = HDIM;   g = 8  + (kk >> 4); }
    else                 { kk = kidx - 384; W = W3; Kreal = HDIM;   g = 24 + (kk >> 4); }
    float w = (kk < Kreal) ? W[kk * HDIM + n] : 0.0f;
    __nv_bfloat16 hi = __float2bfloat16(w);
    __nv_bfloat16 lo = __float2bfloat16(w - __bfloat162float(hi));
    int kc = kk & 15;
    int s  = n >> 5, nn = n & 31, q = nn >> 4;
    int j  = ((nn >> 3) & 1) * 2 + ((kc >> 3) & 1);
    int L  = (nn & 7) * 4 + ((kc & 7) >> 1);
    size_t base = ((size_t)g * 2) * 8192 + (size_t)s * 1024
                + (size_t)q * 512 + (size_t)L * 16 + (size_t)j * 4 + (size_t)(kc & 1) * 2;
    *(__nv_bfloat16*)((char*)WCH + base)        = hi;
    *(__nv_bfloat16*)((char*)WCH + base + 8192) = lo;   // lo image
}

// ---- main kernel ----
__global__ void __launch_bounds__(THREADS, 2)
gnn_mma_kernel(const float* __restrict__ ea,
               const float* __restrict__ b1, const float* __restrict__ b2,
               const float* __restrict__ b3,
               const float* __restrict__ W4, const float* __restrict__ b4,
               float* __restrict__ out, int ntot)
{
    extern __shared__ char smem[];
    const uint32_t sbase = smem_u32(smem);
    const int tid = threadIdx.x, lane = tid & 31, wid = tid >> 5;
    const int row0 = blockIdx.x * TILE_M;

    // e-tile: [m][k0..127] bf16 hi/lo, swizzled (k>=100 zero)
#pragma unroll
    for (int i = 0; i < 32; i++) {
        int idx = tid + i * THREADS;        // 64*128
        int m = idx >> 7, k = idx & 127;
        int row = row0 + m;
        float v = (k < K1REAL && row < ntot) ? ea[(size_t)row * K1REAL + k] : 0.0f;
        __nv_bfloat16 hi = __float2bfloat16(v);
        __nv_bfloat16 lo = __float2bfloat16(v - __bfloat162float(hi));
        uint32_t off = act_off(m, k);
        *(__nv_bfloat16*)(smem + SM_ACT_HI + off) = hi;
        *(__nv_bfloat16*)(smem + SM_ACT_LO + off) = lo;
    }
    __syncthreads();

    // A ldsm addressing (loop-invariant)
    const int midx = lane >> 3, l7 = lane & 7;
    const int arow = (midx & 1) * 8 + l7;               // 0..15
    const uint32_t a_base = (uint32_t)arow * 512u;
    const uint32_t a_sw   = ((uint32_t)arow & 7u) << 4;
    const uint32_t a_k2   = (uint32_t)(midx >> 1) * 16u;

    // per-lane fragment-linear weight pointer
    const char* wlane = (const char*)WCH + (size_t)wid * 1024 + (size_t)lane * 16;

    float acc[4][4][4];
#pragma unroll
    for (int mt = 0; mt < 4; mt++)
#pragma unroll
        for (int nt = 0; nt < 4; nt++)
#pragma unroll
            for (int x = 0; x < 4; x++) acc[mt][nt][x] = 0.0f;

    const int r = lane >> 2, cp2 = (lane & 3) * 2;
    int gbase = 0;

#pragma unroll
    for (int l = 0; l < 3; l++) {
        const int nch = (l == 0) ? 8 : 16;
        for (int ci = 0; ci < nch; ci++) {
            const char* wp = wlane + (size_t)(gbase + ci) * 16384;
            // B fragments straight from global (L1/L2-cached)
            uint4 h0 = __ldg((const uint4*)(wp));
            uint4 h1 = __ldg((const uint4*)(wp + 512));
            uint4 l0 = __ldg((const uint4*)(wp + 8192));
            uint4 l1 = __ldg((const uint4*)(wp + 8192 + 512));
            uint32_t bh[8] = { h0.x, h0.y, h0.z, h0.w, h1.x, h1.y, h1.z, h1.w };
            uint32_t bl_[8] = { l0.x, l0.y, l0.z, l0.w, l1.x, l1.y, l1.z, l1.w };

            const uint32_t abase = sbase + a_base + (((uint32_t)ci * 32u + a_k2) ^ a_sw);
            uint32_t a[16];
            // pass 1: A_lo x B_hi
#pragma unroll
            for (int mt = 0; mt < 4; mt++) ldsm_x4(a + mt * 4, abase + 32768 + mt * 8192);
#pragma unroll
            for (int nt = 0; nt < 4; nt++) {
                uint32_t bx = bh[(nt >> 1) * 4 + (nt & 1) * 2];
                uint32_t by = bh[(nt >> 1) * 4 + (nt & 1) * 2 + 1];
#pragma unroll
                for (int mt = 0; mt < 4; mt++) mma_bf16(acc[mt][nt], a + mt * 4, bx, by);
            }
            // pass 2: A_hi x B_hi (reuse a regs)
#pragma unroll
            for (int mt = 0; mt < 4; mt++) ldsm_x4(a + mt * 4, abase + mt * 8192);
#pragma unroll
            for (int nt = 0; nt < 4; nt++) {
                uint32_t bx = bh[(nt >> 1) * 4 + (nt & 1) * 2];
                uint32_t by = bh[(nt >> 1) * 4 + (nt & 1) * 2 + 1];
#pragma unroll
                for (int mt = 0; mt < 4; mt++) mma_bf16(acc[mt][nt], a + mt * 4, bx, by);
            }
            // pass 3: A_hi x B_lo
#pragma unroll
            for (int nt = 0; nt < 4; nt++) {
                uint32_t bx = bl_[(nt >> 1) * 4 + (nt & 1) * 2];
                uint32_t by = bl_[(nt >> 1) * 4 + (nt & 1) * 2 + 1];
#pragma unroll
                for (int mt = 0; mt < 4; mt++) mma_bf16(acc[mt][nt], a + mt * 4, bx, by);
            }
        }
        gbase += nch;

        __syncthreads();   // all act reads of this layer done
        const float* bl = (l == 0) ? b1 : (l == 1) ? b2 : b3;
#pragma unroll
        for (int nt = 0; nt < 4; nt++) {
            int n = wid * 32 + nt * 8 + cp2;
            float bn0 = __ldg(bl + n), bn1 = __ldg(bl + n + 1);
#pragma unroll
            for (int mt = 0; mt < 4; mt++)
#pragma unroll
                for (int dp = 0; dp < 2; dp++) {
                    int m = mt * 16 + r + dp * 8;
                    float t0 = tanh_fast(acc[mt][nt][dp * 2]     + bn0);
                    float t1 = tanh_fast(acc[mt][nt][dp * 2 + 1] + bn1);
                    float h0 = __bfloat162float(__float2bfloat16(t0));
                    float h1 = __bfloat162float(__float2bfloat16(t1));
                    uint32_t off = act_off(m, n);
                    *(uint32_t*)(smem + SM_ACT_HI + off) = pack_bf2(t0, t1);
                    *(uint32_t*)(smem + SM_ACT_LO + off) = pack_bf2(t0 - h0, t1 - h1);
                    acc[mt][nt][dp * 2] = 0.0f; acc[mt][nt][dp * 2 + 1] = 0.0f;
                }
        }
        __syncthreads();   // act writes visible before next layer's ldsm
    }

    // layer 4: out[m] = sigmoid( sum_k act[m][k]*W4[k] + b4 ), 4 thr/row
    {
        int m = tid >> 2, seg = tid & 3;
        uint32_t base = (uint32_t)m * 512u, sw = ((uint32_t)m & 7u) << 4;
        float s = 0.f;
#pragma unroll
        for (int q = 0; q < 32; q++) {
            uint32_t off = base + (((uint32_t)(seg * 128 + q * 4)) ^ sw);
            __nv_bfloat162 h2 = *(const __nv_bfloat162*)(smem + SM_ACT_HI + off);
            __nv_bfloat162 l2 = *(const __nv_bfloat162*)(smem + SM_ACT_LO + off);
            float2 w2 = __ldg((const float2*)(W4 + seg * 64 + q * 2));
            s += (__bfloat162float(h2.x) + __bfloat162float(l2.x)) * w2.x
               + (__bfloat162float(h2.y) + __bfloat162float(l2.y)) * w2.y;
        }
        s += __shfl_down_sync(0xffffffff, s, 2);
        s += __shfl_down_sync(0xffffffff, s, 1);
        if (seg == 0) {
            float z = s + __ldg(b4);
            int row = row0 + m;
            if (row < ntot) out[row] = 1.0f / (1.0f + expf(-z));
        }
    }
}

extern "C" void kernel_launch(void* const* d_in, const int* in_sizes, int n_in,
                              void* d_out, int out_size)
{
    // Inputs: x, edge_index, edge_attr, W1, b1, W2, b2, W3, b3, W4, b4
    const float* ea = (const float*)d_in[2];
    const float* W1 = (const float*)d_in[3];
    const float* b1 = (const float*)d_in[4];
    const float* W2 = (const float*)d_in[5];
    const float* b2 = (const float*)d_in[6];
    const float* W3 = (const float*)d_in[7];
    const float* b3 = (const float*)d_in[8];
    const float* W4 = (const float*)d_in[9];
    const float* b4 = (const float*)d_in[10];
    float* out = (float*)d_out;

    int ntot = out_size;                              // 500000
    int grid = (ntot + TILE_M - 1) / TILE_M;          // 7813

    wsplit_kernel<<<640, 256>>>(W1, W2, W3);

    cudaFuncSetAttribute(gnn_mma_kernel,
                         cudaFuncAttributeMaxDynamicSharedMemorySize, SMEM_TOTAL);
    gnn_mma_kernel<<<grid, THREADS, SMEM_TOTAL>>>(ea, b1, b2, b3, W4, b4, out, ntot);
}

// round 12
// speedup vs baseline: 1.5521x; 1.1220x over previous
#include <cuda_runtime.h>
#include <cuda_bf16.h>
#include <cstdint>

#define K1REAL  100
#define HDIM    256
#define TILE_M  64
#define THREADS 256            // 8 warps; warp w owns m0..63 x n[w*32, w*32+32)
#define NCHUNK  39             // k16 chunks: L1 7 (k pad 112), L2 16, L3 16

#define SM_ACT_HI 0            // 64 x 512B, XOR-swizzled
#define SM_ACT_LO 32768
#define SMEM_TOTAL 65536       // act only (layer-4 partials reuse offset 0)

// fragment-linear weights (40 slots; slot 39 is prefetch-overread pad)
__device__ __nv_bfloat16 WCH[(size_t)40 * 2 * 4096];

__device__ __forceinline__ uint32_t smem_u32(const void* p) {
    uint32_t a;
    asm("{ .reg .u64 t; cvta.to.shared.u64 t, %1; cvt.u32.u64 %0, t; }" : "=r"(a) : "l"(p));
    return a;
}
__device__ __forceinline__ void ldsm_x4(uint32_t r[4], uint32_t addr) {
    asm volatile("ldmatrix.sync.aligned.m8n8.x4.shared.b16 {%0,%1,%2,%3}, [%4];"
                 : "=r"(r[0]), "=r"(r[1]), "=r"(r[2]), "=r"(r[3]) : "r"(addr));
}
__device__ __forceinline__ void mma_bf16(float d[4], const uint32_t a[4],
                                         uint32_t b0, uint32_t b1) {
    asm volatile(
        "mma.sync.aligned.m16n8k16.row.col.f32.bf16.bf16.f32 "
        "{%0,%1,%2,%3}, {%4,%5,%6,%7}, {%8,%9}, {%0,%1,%2,%3};"
        : "+f"(d[0]), "+f"(d[1]), "+f"(d[2]), "+f"(d[3])
        : "r"(a[0]), "r"(a[1]), "r"(a[2]), "r"(a[3]), "r"(b0), "r"(b1));
}
__device__ __forceinline__ float tanh_fast(float x) {
    float y; asm("tanh.approx.f32 %0, %1;" : "=f"(y) : "f"(x)); return y;
}
__device__ __forceinline__ uint32_t pack_bf2(float a, float b) {
    __nv_bfloat162 t;
    t.x = __float2bfloat16(a); t.y = __float2bfloat16(b);
    return *reinterpret_cast<uint32_t*>(&t);
}
// act element (m, k): byte offset m*512 + ((k*2) ^ ((m&7)<<4))  (verified R8-R11)
__device__ __forceinline__ uint32_t act_off(int m, int k) {
    return (uint32_t)m * 512u + (((uint32_t)k * 2u) ^ (((uint32_t)m & 7u) << 4));
}

// ---- weight pre-split into fragment-linear layout (verified R11) ----
// grid 624: kidx = padded-k (L1 pad 112, L2/L3 256)
__global__ void wsplit_kernel(const float* __restrict__ W1,
                              const float* __restrict__ W2,
                              const float* __restrict__ W3) {
    int n = threadIdx.x;
    int kidx = blockIdx.x;                  // 0..623
    const float* W; int kk, Kreal, g;
    if (kidx < 112)      { kk = kidx;       W = W1; Kreal = K1REAL; g = kk >> 4; }
    else if (kidx < 368) { kk = kidx - 112; W = W2; Kreal = HDIM;   g = 7  + (kk >> 4); }
    else                 { kk = kidx - 368; W = W3; Kreal = HDIM;   g = 23 + (kk >> 4); }
    float w = (kk < Kreal) ? W[kk * HDIM + n] : 0.0f;
    __nv_bfloat16 hi = __float2bfloat16(w);
    __nv_bfloat16 lo = __float2bfloat16(w - __bfloat162float(hi));
    int kc = kk & 15;
    int s  = n >> 5, nn = n & 31, q = nn >> 4;
    int j  = ((nn >> 3) & 1) * 2 + ((kc >> 3) & 1);
    int L  = (nn & 7) * 4 + ((kc & 7) >> 1);
    size_t base = ((size_t)g * 2) * 8192 + (size_t)s * 1024
                + (size_t)q * 512 + (size_t)L * 16 + (size_t)j * 4 + (size_t)(kc & 1) * 2;
    *(__nv_bfloat16*)((char*)WCH + base)        = hi;
    *(__nv_bfloat16*)((char*)WCH + base + 8192) = lo;
}

// ---- main kernel ----
__global__ void __launch_bounds__(THREADS, 2)
gnn_mma_kernel(const float* __restrict__ ea,
               const float* __restrict__ b1, const float* __restrict__ b2,
               const float* __restrict__ b3,
               const float* __restrict__ W4, const float* __restrict__ b4,
               float* __restrict__ out, int ntot)
{
    extern __shared__ char smem[];
    const uint32_t sbase = smem_u32(smem);
    const int tid = threadIdx.x, lane = tid & 31, wid = tid >> 5;
    const int row0 = blockIdx.x * TILE_M;

    // e-tile: [m][k0..127] bf16 hi/lo, swizzled (k>=100 zero; only k<112 used)
#pragma unroll
    for (int i = 0; i < 32; i++) {
        int idx = tid + i * THREADS;        // 64*128
        int m = idx >> 7, k = idx & 127;
        int row = row0 + m;
        float v = (k < K1REAL && row < ntot) ? ea[(size_t)row * K1REAL + k] : 0.0f;
        __nv_bfloat16 hi = __float2bfloat16(v);
        __nv_bfloat16 lo = __float2bfloat16(v - __bfloat162float(hi));
        uint32_t off = act_off(m, k);
        *(__nv_bfloat16*)(smem + SM_ACT_HI + off) = hi;
        *(__nv_bfloat16*)(smem + SM_ACT_LO + off) = lo;
    }
    __syncthreads();

    // A ldsm addressing (loop-invariant)
    const int midx = lane >> 3, l7 = lane & 7;
    const int arow = (midx & 1) * 8 + l7;               // 0..15
    const uint32_t a_base = (uint32_t)arow * 512u;
    const uint32_t a_sw   = ((uint32_t)arow & 7u) << 4;
    const uint32_t a_k2   = (uint32_t)(midx >> 1) * 16u;

    const char* wlane = (const char*)WCH + (size_t)wid * 1024 + (size_t)lane * 16;

    float acc[4][4][4];
#pragma unroll
    for (int mt = 0; mt < 4; mt++)
#pragma unroll
        for (int nt = 0; nt < 4; nt++)
#pragma unroll
            for (int x = 0; x < 4; x++) acc[mt][nt][x] = 0.0f;

    const int r = lane >> 2, cp2 = (lane & 3) * 2;
    int gbase = 0;

    // preload B-hi fragments for chunk 0
    uint32_t bh[8];
    {
        uint4 t0 = __ldg((const uint4*)wlane);
        uint4 t1 = __ldg((const uint4*)(wlane + 512));
        bh[0]=t0.x; bh[1]=t0.y; bh[2]=t0.z; bh[3]=t0.w;
        bh[4]=t1.x; bh[5]=t1.y; bh[6]=t1.z; bh[7]=t1.w;
    }

#pragma unroll
    for (int l = 0; l < 3; l++) {
        const int nch = (l == 0) ? 7 : 16;
        for (int ci = 0; ci < nch; ci++) {
            const int g = gbase + ci;
            const char* wp = wlane + (size_t)g * 16384;
            // B-lo for this chunk (used only in pass 3 -> latency self-covered)
            uint4 l0 = __ldg((const uint4*)(wp + 8192));
            uint4 l1 = __ldg((const uint4*)(wp + 8192 + 512));
            // prefetch next chunk's B-hi (used next iteration)
            const char* wpn = wlane + (size_t)(g + 1) * 16384;
            uint4 p0 = __ldg((const uint4*)wpn);
            uint4 p1 = __ldg((const uint4*)(wpn + 512));

            const uint32_t abase = sbase + a_base + (((uint32_t)ci * 32u + a_k2) ^ a_sw);
            uint32_t a[16];
            // pass 1: A_lo x B_hi
#pragma unroll
            for (int mt = 0; mt < 4; mt++) ldsm_x4(a + mt * 4, abase + 32768 + mt * 8192);
#pragma unroll
            for (int nt = 0; nt < 4; nt++) {
                uint32_t bx = bh[(nt >> 1) * 4 + (nt & 1) * 2];
                uint32_t by = bh[(nt >> 1) * 4 + (nt & 1) * 2 + 1];
#pragma unroll
                for (int mt = 0; mt < 4; mt++) mma_bf16(acc[mt][nt], a + mt * 4, bx, by);
            }
            // pass 2: A_hi x B_hi
#pragma unroll
            for (int mt = 0; mt < 4; mt++) ldsm_x4(a + mt * 4, abase + mt * 8192);
#pragma unroll
            for (int nt = 0; nt < 4; nt++) {
                uint32_t bx = bh[(nt >> 1) * 4 + (nt & 1) * 2];
                uint32_t by = bh[(nt >> 1) * 4 + (nt & 1) * 2 + 1];
#pragma unroll
                for (int mt = 0; mt < 4; mt++) mma_bf16(acc[mt][nt], a + mt * 4, bx, by);
            }
            // pass 3: A_hi x B_lo
            uint32_t bl_[8] = { l0.x, l0.y, l0.z, l0.w, l1.x, l1.y, l1.z, l1.w };
#pragma unroll
            for (int nt = 0; nt < 4; nt++) {
                uint32_t bx = bl_[(nt >> 1) * 4 + (nt & 1) * 2];
                uint32_t by = bl_[(nt >> 1) * 4 + (nt & 1) * 2 + 1];
#pragma unroll
                for (int mt = 0; mt < 4; mt++) mma_bf16(acc[mt][nt], a + mt * 4, bx, by);
            }
            // rotate prefetched B-hi in
            bh[0]=p0.x; bh[1]=p0.y; bh[2]=p0.z; bh[3]=p0.w;
            bh[4]=p1.x; bh[5]=p1.y; bh[6]=p1.z; bh[7]=p1.w;
        }
        gbase += nch;

        __syncthreads();   // all act reads of this layer done

        if (l < 2) {
            const float* bl = (l == 0) ? b1 : b2;
#pragma unroll
            for (int nt = 0; nt < 4; nt++) {
                int n = wid * 32 + nt * 8 + cp2;
                float bn0 = __ldg(bl + n), bn1 = __ldg(bl + n + 1);
#pragma unroll
                for (int mt = 0; mt < 4; mt++)
#pragma unroll
                    for (int dp = 0; dp < 2; dp++) {
                        int m = mt * 16 + r + dp * 8;
                        float t0 = tanh_fast(acc[mt][nt][dp * 2]     + bn0);
                        float t1 = tanh_fast(acc[mt][nt][dp * 2 + 1] + bn1);
                        float h0 = __bfloat162float(__float2bfloat16(t0));
                        float h1 = __bfloat162float(__float2bfloat16(t1));
                        uint32_t off = act_off(m, n);
                        *(uint32_t*)(smem + SM_ACT_HI + off) = pack_bf2(t0, t1);
                        *(uint32_t*)(smem + SM_ACT_LO + off) = pack_bf2(t0 - h0, t1 - h1);
                        acc[mt][nt][dp * 2] = 0.0f; acc[mt][nt][dp * 2 + 1] = 0.0f;
                    }
            }
            __syncthreads();   // act writes visible before next layer's ldsm
        } else {
            // fused layer 3 epilogue + layer 4: dot tanh(acc+b3) with W4 in regs
            float part[8];     // idx = mt*2 + dp, m = mt*16 + r + dp*8
#pragma unroll
            for (int i = 0; i < 8; i++) part[i] = 0.0f;
#pragma unroll
            for (int nt = 0; nt < 4; nt++) {
                int n = wid * 32 + nt * 8 + cp2;
                float bn0 = __ldg(b3 + n), bn1 = __ldg(b3 + n + 1);
                float2 w2 = __ldg((const float2*)(W4 + n));
#pragma unroll
                for (int mt = 0; mt < 4; mt++)
#pragma unroll
                    for (int dp = 0; dp < 2; dp++) {
                        float t0 = tanh_fast(acc[mt][nt][dp * 2]     + bn0);
                        float t1 = tanh_fast(acc[mt][nt][dp * 2 + 1] + bn1);
                        part[mt * 2 + dp] += t0 * w2.x + t1 * w2.y;
                    }
            }
            // quad reduce (lanes 4r..4r+3 share the same 8 m-rows)
#pragma unroll
            for (int i = 0; i < 8; i++) {
                part[i] += __shfl_xor_sync(0xffffffff, part[i], 1);
                part[i] += __shfl_xor_sync(0xffffffff, part[i], 2);
            }
            // per-warp partials -> smem (reuse act area; safe after barrier above)
            float* psm = (float*)smem;   // [8 warps][64 m]
            if ((lane & 3) == 0) {
#pragma unroll
                for (int mt = 0; mt < 4; mt++)
#pragma unroll
                    for (int dp = 0; dp < 2; dp++)
                        psm[wid * 64 + mt * 16 + r + dp * 8] = part[mt * 2 + dp];
            }
            __syncthreads();
            if (tid < TILE_M) {
                float s = 0.0f;
#pragma unroll
                for (int w = 0; w < 8; w++) s += psm[w * 64 + tid];
                float z = s + __ldg(b4);
                int row = row0 + tid;
                if (row < ntot) out[row] = 1.0f / (1.0f + expf(-z));
            }
        }
    }
}

extern "C" void kernel_launch(void* const* d_in, const int* in_sizes, int n_in,
                              void* d_out, int out_size)
{
    // Inputs: x, edge_index, edge_attr, W1, b1, W2, b2, W3, b3, W4, b4
    const float* ea = (const float*)d_in[2];
    const float* W1 = (const float*)d_in[3];
    const float* b1 = (const float*)d_in[4];
    const float* W2 = (const float*)d_in[5];
    const float* b2 = (const float*)d_in[6];
    const float* W3 = (const float*)d_in[7];
    const float* b3 = (const float*)d_in[8];
    const float* W4 = (const float*)d_in[9];
    const float* b4 = (const float*)d_in[10];
    float* out = (float*)d_out;

    int ntot = out_size;                              // 500000
    int grid = (ntot + TILE_M - 1) / TILE_M;          // 7813

    wsplit_kernel<<<624, 256>>>(W1, W2, W3);

    cudaFuncSetAttribute(gnn_mma_kernel,
                         cudaFuncAttributeMaxDynamicSharedMemorySize, SMEM_TOTAL);
    gnn_mma_kernel<<<grid, THREADS, SMEM_TOTAL>>>(ea, b1, b2, b3, W4, b4, out, ntot);
}